// round 10
// baseline (speedup 1.0000x reference)
#include <cuda_runtime.h>
#include <cuda_bf16.h>

#define T_TOK 20000
#define LDO   160

// ---------------- scratch ----------------
__device__ __align__(256) float g_AH1[T_TOK * LDO];
__device__ __align__(256) float g_AP [T_TOK * LDO];
__device__ __align__(256) float g_BP [T_TOK * LDO];
__device__ __align__(256) float g_PP [(T_TOK + 64) * LDO];  // 64 zero pad rows
__device__ __align__(256) float g_LG [T_TOK];
__device__ int g_ctr;
__device__ unsigned g_maxbits;

// weight images: per k16-chunk: 160 rows(n) x 40 bf16 (16 hi | 16 lo | 8 pad)
#define CH_ELEMS 6400
#define O_A1 0
#define O_SA (25 * CH_ELEMS)
#define O_SB (50 * CH_ELEMS)
#define O_SP (75 * CH_ELEMS)
#define O_A2 (94 * CH_ELEMS)
#define O_W2 (104 * CH_ELEMS)
__device__ __align__(256) __nv_bfloat16 g_Wimg[114 * CH_ELEMS];

__device__ __align__(256) float g_ba1[160];
__device__ __align__(256) float g_ba2[160];
__device__ __align__(256) float g_b1 [160];
__device__ __align__(256) float g_b2 [160];
__device__ __align__(256) float g_w3 [160];
__device__ __align__(256) float g_wa3[160];

// ---------------- helpers ----------------
__device__ __forceinline__ unsigned cvta_s(const void* p) {
    return (unsigned)__cvta_generic_to_shared(p);
}
__device__ __forceinline__ void ldmx4(unsigned* r, unsigned addr) {
    asm volatile("ldmatrix.sync.aligned.m8n8.x4.shared.b16 {%0,%1,%2,%3}, [%4];"
        : "=r"(r[0]), "=r"(r[1]), "=r"(r[2]), "=r"(r[3]) : "r"(addr));
}
__device__ __forceinline__ void mma16816(float* d, const unsigned* a, const unsigned* b) {
    asm volatile(
        "mma.sync.aligned.m16n8k16.row.col.f32.bf16.bf16.f32 "
        "{%0,%1,%2,%3}, {%4,%5,%6,%7}, {%8,%9}, {%0,%1,%2,%3};"
        : "+f"(d[0]), "+f"(d[1]), "+f"(d[2]), "+f"(d[3])
        : "r"(a[0]), "r"(a[1]), "r"(a[2]), "r"(a[3]), "r"(b[0]), "r"(b[1]));
}
__device__ __forceinline__ void split_bf16(float v, unsigned short& h, unsigned short& l) {
    __nv_bfloat16 hb = __float2bfloat16_rn(v);
    __nv_bfloat16 lb = __float2bfloat16_rn(v - __bfloat162float(hb));
    h = __bfloat16_as_ushort(hb);
    l = __bfloat16_as_ushort(lb);
}
__device__ __forceinline__ unsigned encf(float x) {
    unsigned u = __float_as_uint(x);
    return (u & 0x80000000u) ? ~u : (u | 0x80000000u);
}
__device__ __forceinline__ float decf(unsigned u) {
    unsigned b = (u & 0x80000000u) ? (u & 0x7fffffffu) : ~u;
    return __uint_as_float(b);
}

// ---------------- single fused prep ----------------
__global__ void prep_all(const float* __restrict__ aW1, const float* __restrict__ scW1,
                         const float* __restrict__ aW2, const float* __restrict__ scW2,
                         const float* __restrict__ ab1, const float* __restrict__ ab2,
                         const float* __restrict__ sb1, const float* __restrict__ sb2,
                         const float* __restrict__ sW3, const float* __restrict__ aW3)
{
    int tid = threadIdx.x;
    if (blockIdx.x == 0) {
        if (tid < 160) {
            bool ok = tid < 150;
            g_ba1[tid] = ok ? ab1[tid] : 0.f;
            g_ba2[tid] = ok ? ab2[tid] : 0.f;
            g_b1 [tid] = ok ? sb1[tid] : 0.f;
            g_b2 [tid] = ok ? sb2[tid] : 0.f;
            g_w3 [tid] = ok ? sW3[tid] : 0.f;
            g_wa3[tid] = ok ? aW3[tid] : 0.f;
        }
        if (tid == 0) { g_ctr = 0; g_maxbits = 0u; }
    }
    const int total = 114 * 2560;
    for (int idx = blockIdx.x * blockDim.x + tid; idx < total;
         idx += gridDim.x * blockDim.x) {
        int c   = idx / 2560;
        int rem = idx - c * 2560;
        int nn  = rem >> 4;
        int kk  = rem & 15;
        const float* W; int K; int lc;
        if      (c < 25)  { W = aW1;             K = 400; lc = c;       }
        else if (c < 50)  { W = scW1;            K = 400; lc = c - 25;  }
        else if (c < 75)  { W = scW1 + 400*150;  K = 400; lc = c - 50;  }
        else if (c < 94)  { W = scW1 + 800*150;  K = 300; lc = c - 75;  }
        else if (c < 104) { W = aW2;             K = 150; lc = c - 94;  }
        else              { W = scW2;            K = 150; lc = c - 104; }
        int k = lc * 16 + kk;
        float v = (k < K && nn < 150) ? W[k * 150 + nn] : 0.f;
        unsigned short h, l;
        split_bf16(v, h, l);
        unsigned short* dst = (unsigned short*)(g_Wimg + (size_t)c * CH_ELEMS + nn * 40);
        dst[kk]      = h;
        dst[16 + kk] = l;
        if (kk < 8) dst[32 + kk] = 0;
    }
}

// ---------------- staging (512 threads, 128-row tiles) ----------------
__device__ __forceinline__ void stage_A128(const float* __restrict__ X, int ldx,
                                           int Kreal, int m0, int M, int c,
                                           __nv_bfloat16* __restrict__ Abuf, int tid)
{
    int r  = tid >> 2;
    int kq = tid & 3;
    int m  = m0 + r;
    int k0 = c * 16 + kq * 4;
    float4 v = make_float4(0.f, 0.f, 0.f, 0.f);
    if (m < M) {
        if (k0 + 3 < Kreal) {
            v = *(const float4*)(X + (size_t)m * ldx + k0);
        } else {
            float* pv = (float*)&v;
            for (int j = 0; j < 4; j++)
                if (k0 + j < Kreal) pv[j] = X[(size_t)m * ldx + k0 + j];
        }
    }
    unsigned short h[4], l[4];
    split_bf16(v.x, h[0], l[0]); split_bf16(v.y, h[1], l[1]);
    split_bf16(v.z, h[2], l[2]); split_bf16(v.w, h[3], l[3]);
    unsigned short* dst = (unsigned short*)(Abuf + r * 40 + kq * 4);
    *(uint2*)dst        = make_uint2((unsigned)h[0] | ((unsigned)h[1] << 16),
                                     (unsigned)h[2] | ((unsigned)h[3] << 16));
    *(uint2*)(dst + 16) = make_uint2((unsigned)l[0] | ((unsigned)l[1] << 16),
                                     (unsigned)l[2] | ((unsigned)l[3] << 16));
}

__device__ __forceinline__ void stage_B512(const __nv_bfloat16* __restrict__ img, int c,
                                           __nv_bfloat16* __restrict__ Bbuf, int tid)
{
    const float4* src = (const float4*)(img + (size_t)c * CH_ELEMS);
    float4* dst = (float4*)Bbuf;
    for (int i = tid; i < 800; i += 512) dst[i] = src[i];
}

// ---------------- core MMA macro (16 rows x 80 cols per warp) ----------------
#define MMA_CHUNK(aBuf, bBuf)                                                   \
    {                                                                           \
        unsigned ah[4], al[4];                                                  \
        ldmx4(ah, (aBuf) + aOff);                                               \
        ldmx4(al, (aBuf) + aOff + 32);                                          \
        _Pragma("unroll")                                                       \
        for (int p = 0; p < 5; p++) {                                           \
            unsigned bh[4], bl[4];                                              \
            unsigned baddr = (bBuf) + (unsigned)((nw * 80 + p * 16) * 80) + bOff; \
            ldmx4(bh, baddr);                                                   \
            ldmx4(bl, baddr + 32);                                              \
            mma16816(acc[2 * p],     ah, bh);                                   \
            mma16816(acc[2 * p],     ah, bl);                                   \
            mma16816(acc[2 * p],     al, bh);                                   \
            mma16816(acc[2 * p + 1], ah, bh + 2);                               \
            mma16816(acc[2 * p + 1], ah, bl + 2);                               \
            mma16816(acc[2 * p + 1], al, bh + 2);                               \
        }                                                                       \
    }

// span 16-warp layout: 16 rows x 40 cols, hi+lo B fused in one ldmatrix.x4
#define MMA_CHUNK_W(aBuf, bBuf)                                                 \
    {                                                                           \
        unsigned ah[4], al[4];                                                  \
        ldmx4(ah, (aBuf) + aOff);                                               \
        ldmx4(al, (aBuf) + aOff + 32);                                          \
        _Pragma("unroll")                                                       \
        for (int p = 0; p < 5; p++) {                                           \
            unsigned bb[4];                                                     \
            unsigned baddr = (bBuf) + (unsigned)((nw * 40 + p * 8) * 80) + bOff4; \
            ldmx4(bb, baddr);                                                   \
            mma16816(acc[p], ah, bb);                                           \
            mma16816(acc[p], ah, bb + 2);                                       \
            mma16816(acc[p], al, bb);                                           \
        }                                                                       \
    }

// ---------------- batched GEMM: 4 jobs, 128-row tiles, 512 threads ----------------
__global__ __launch_bounds__(512, 1) void gemmA(
    const float* __restrict__ states, const float* __restrict__ embeds,
    float* __restrict__ AH1, float* __restrict__ AP,
    float* __restrict__ BP,  float* __restrict__ PP)
{
    __shared__ __nv_bfloat16 As[2 * 128 * 40];
    __shared__ __nv_bfloat16 Bs[2 * 160 * 40];

    const float* X; int ldx, Kreal, chunks; const __nv_bfloat16* img;
    const float* biasPad; int dorelu; float* Y;
    switch (blockIdx.y) {
        case 0: X = states; ldx = 400; Kreal = 400; chunks = 25;
                img = g_Wimg + O_A1; biasPad = g_ba1; dorelu = 1; Y = AH1; break;
        case 1: X = states; ldx = 400; Kreal = 400; chunks = 25;
                img = g_Wimg + O_SA; biasPad = nullptr; dorelu = 0; Y = AP; break;
        case 2: X = states; ldx = 400; Kreal = 400; chunks = 25;
                img = g_Wimg + O_SB; biasPad = nullptr; dorelu = 0; Y = BP; break;
        default: X = embeds; ldx = 300; Kreal = 300; chunks = 19;
                img = g_Wimg + O_SP; biasPad = nullptr; dorelu = 0; Y = PP; break;
    }
    const int M = T_TOK;
    const int tid  = threadIdx.x;
    const int lane = tid & 31;
    const int warp = tid >> 5;
    const int mw   = warp & 7;
    const int nw   = warp >> 3;
    const int m0   = blockIdx.x * 128;

    float acc[10][4];
#pragma unroll
    for (int t = 0; t < 10; t++)
#pragma unroll
        for (int j = 0; j < 4; j++) acc[t][j] = 0.f;

    const int aRow = (lane & 7) + ((lane & 8) ? 8 : 0);
    const unsigned aOff = (unsigned)((mw * 16 + aRow) * 80 + ((lane & 16) ? 16 : 0));
    const int bRow = (lane & 7) + ((lane & 16) ? 8 : 0);
    const unsigned bOff = (unsigned)(bRow * 80 + ((lane & 8) ? 16 : 0));
    const unsigned asBase = cvta_s(As);
    const unsigned bsBase = cvta_s(Bs);

    stage_A128(X, ldx, Kreal, m0, M, 0, As, tid);
    stage_B512(img, 0, Bs, tid);
    __syncthreads();

    for (int c = 0; c < chunks; c++) {
        int cur = c & 1;
        if (c + 1 < chunks) {
            stage_A128(X, ldx, Kreal, m0, M, c + 1, As + (cur ^ 1) * 5120, tid);
            stage_B512(img, c + 1, Bs + (cur ^ 1) * 6400, tid);
        }
        unsigned aBuf = asBase + cur * 10240;
        unsigned bBuf = bsBase + cur * 12800;
        MMA_CHUNK(aBuf, bBuf);
        __syncthreads();
    }

    const int r1 = m0 + mw * 16 + (lane >> 2);
    const int cBase = nw * 80 + 2 * (lane & 3);
#pragma unroll
    for (int t = 0; t < 10; t++) {
        int col = cBase + t * 8;
        float b0 = 0.f, b1v = 0.f;
        if (biasPad) { b0 = biasPad[col]; b1v = biasPad[col + 1]; }
        float2 vA = make_float2(acc[t][0] + b0, acc[t][1] + b1v);
        float2 vB = make_float2(acc[t][2] + b0, acc[t][3] + b1v);
        if (dorelu) {
            vA.x = fmaxf(vA.x, 0.f); vA.y = fmaxf(vA.y, 0.f);
            vB.x = fmaxf(vB.x, 0.f); vB.y = fmaxf(vB.y, 0.f);
        }
        if (r1 < M)     *(float2*)(Y + (size_t)r1 * LDO + col)       = vA;
        if (r1 + 8 < M) *(float2*)(Y + (size_t)(r1 + 8) * LDO + col) = vB;
    }
}

// ---------------- attn layer2 + fused logits + global max (128-row tiles) ----------------
__global__ __launch_bounds__(512, 1) void attn2_k(
    const float* __restrict__ AH1, const float* __restrict__ ab3,
    float* __restrict__ LG)
{
    __shared__ __nv_bfloat16 As[2 * 128 * 40];
    __shared__ __nv_bfloat16 Bs[2 * 160 * 40];
    __shared__ float red2[256];
    __shared__ float bmax[4];

    const int tid  = threadIdx.x;
    const int lane = tid & 31;
    const int warp = tid >> 5;
    const int mw   = warp & 7;
    const int nw   = warp >> 3;
    const int m0   = blockIdx.x * 128;
    const int M    = T_TOK;
    const __nv_bfloat16* img = g_Wimg + O_A2;

    float acc[10][4];
#pragma unroll
    for (int t = 0; t < 10; t++)
#pragma unroll
        for (int j = 0; j < 4; j++) acc[t][j] = 0.f;

    const int aRow = (lane & 7) + ((lane & 8) ? 8 : 0);
    const unsigned aOff = (unsigned)((mw * 16 + aRow) * 80 + ((lane & 16) ? 16 : 0));
    const int bRow = (lane & 7) + ((lane & 16) ? 8 : 0);
    const unsigned bOff = (unsigned)(bRow * 80 + ((lane & 8) ? 16 : 0));
    const unsigned asBase = cvta_s(As);
    const unsigned bsBase = cvta_s(Bs);

    stage_A128(AH1, LDO, 160, m0, M, 0, As, tid);
    stage_B512(img, 0, Bs, tid);
    __syncthreads();

    for (int c = 0; c < 10; c++) {
        int cur = c & 1;
        if (c + 1 < 10) {
            stage_A128(AH1, LDO, 160, m0, M, c + 1, As + (cur ^ 1) * 5120, tid);
            stage_B512(img, c + 1, Bs + (cur ^ 1) * 6400, tid);
        }
        unsigned aBuf = asBase + cur * 10240;
        unsigned bBuf = bsBase + cur * 12800;
        MMA_CHUNK(aBuf, bBuf);
        __syncthreads();
    }

    const int cBase = nw * 80 + 2 * (lane & 3);
    float s1 = 0.f, s2 = 0.f;
#pragma unroll
    for (int t = 0; t < 10; t++) {
        int col = cBase + t * 8;
        float2 b2 = *(const float2*)(g_ba2 + col);
        float2 w3 = *(const float2*)(g_wa3 + col);
        s1 += fmaxf(acc[t][0] + b2.x, 0.f) * w3.x + fmaxf(acc[t][1] + b2.y, 0.f) * w3.y;
        s2 += fmaxf(acc[t][2] + b2.x, 0.f) * w3.x + fmaxf(acc[t][3] + b2.y, 0.f) * w3.y;
    }
    s1 += __shfl_xor_sync(0xffffffffu, s1, 1);
    s1 += __shfl_xor_sync(0xffffffffu, s1, 2);
    s2 += __shfl_xor_sync(0xffffffffu, s2, 1);
    s2 += __shfl_xor_sync(0xffffffffu, s2, 2);
    if ((lane & 3) == 0) {
        int row = mw * 16 + (lane >> 2);
        red2[row * 2 + nw]       = s1;
        red2[(row + 8) * 2 + nw] = s2;
    }
    __syncthreads();
    if (tid < 128) {
        int m = m0 + tid;
        float v = red2[tid * 2] + red2[tid * 2 + 1] + ab3[0];
        float mv = -3.4e38f;
        if (m < M) { LG[m] = v; mv = v; }
#pragma unroll
        for (int o = 16; o; o >>= 1) mv = fmaxf(mv, __shfl_xor_sync(0xffffffffu, mv, o));
        if ((tid & 31) == 0) bmax[tid >> 5] = mv;
    }
    __syncthreads();
    if (tid == 0)
        atomicMax(&g_maxbits, encf(fmaxf(fmaxf(bmax[0], bmax[1]),
                                         fmaxf(bmax[2], bmax[3]))));
}

// ---------------- persistent span kernel: fused NS-update + H1 build ----------------
// smem: W2s 128000 @0, H1s 51200 @128000, NS 40960 @179200, eg 320 @220160,
//       sD 256 @220480, invD 256 @220736, red 1024 @220992 -> 222016
#define SPAN_SMEM 222016
#define N_UNITS (313 * 3)

__global__ __launch_bounds__(512, 1) void span_k(
    const float* __restrict__ AP, const float* __restrict__ BP,
    const float* __restrict__ PP, const float* __restrict__ LG,
    const float* __restrict__ b3, float* __restrict__ out)
{
    extern __shared__ char sm[];
    __nv_bfloat16* W2s = (__nv_bfloat16*)sm;
    __nv_bfloat16* H1s = (__nv_bfloat16*)(sm + 128000);
    float* NS   = (float*)(sm + 179200);
    float* eg   = (float*)(sm + 220160);
    float* sD   = (float*)(sm + 220480);
    float* invD = (float*)(sm + 220736);
    float* red  = (float*)(sm + 220992);
    __shared__ int s_u;

    const int tid  = threadIdx.x;
    const int lane = tid & 31;
    const int warp = tid >> 5;
    const int mw   = warp & 3;   // 16-row group
    const int nw   = warp >> 2;  // 40-col group (0..3)

    const int aRow = (lane & 7) + ((lane & 8) ? 8 : 0);
    const unsigned aOff = (unsigned)((mw * 16 + aRow) * 80 + ((lane & 16) ? 16 : 0));
    const unsigned bOff4 = (unsigned)((lane & 7) * 80 + (((lane >> 3) & 3) * 16));
    const unsigned h1Base = cvta_s(H1s);
    const unsigned w2Base = cvta_s(W2s);

    // load full W2 image (128 KB) once
    {
        const float4* src = (const float4*)(g_Wimg + O_W2);
        float4* dst = (float4*)W2s;
        for (int i = tid; i < 8000; i += 512) dst[i] = src[i];
    }

    const float Mx = decf(g_maxbits);

    while (true) {
        if (tid == 0) s_u = atomicAdd(&g_ctr, 1);
        __syncthreads();
        int u = s_u;
        if (u >= N_UNITS) break;
        int tile = u / 3;
        int grp  = u - tile * 3;
        int s0 = tile * 64;
        int n0   = (grp == 0) ? 1 : (grp == 1 ? 5 : 8);
        int nend = (grp == 0) ? 5 : (grp == 1 ? 8 : 11);

        if (tid < 80) {
            int t = s0 + tid;
            eg[tid] = (t < T_TOK) ? __expf(LG[t] - Mx) : 0.f;
        }
        __syncthreads();

        // init NS / sD to the width-(n0-1) prefix (n0-1 tokens)
#pragma unroll
        for (int it = 0; it < 5; it++) {
            int idx = tid + it * 512;
            int i = idx / 40, g = idx - i * 40, c0 = g * 4;
            float4 a = make_float4(0.f, 0.f, 0.f, 0.f);
            for (int j = 0; j < n0 - 1; j++) {
                float e = eg[i + j];
                float4 p = *(const float4*)(PP + (size_t)(s0 + i + j) * LDO + c0);
                a.x += e * p.x; a.y += e * p.y;
                a.z += e * p.z; a.w += e * p.w;
            }
            *(float4*)(NS + i * 160 + c0) = a;
        }
        if (tid < 64) {
            float d = 0.f;
            for (int j = 0; j < n0 - 1; j++) d += eg[tid + j];
            sD[tid] = d;
        }

        for (int n = n0; n < nend; n++) {
            const int S = T_TOK - n + 1;

            // extend denominator by token n-1
            if (tid < 64) {
                float d = sD[tid] + eg[tid + n - 1];
                sD[tid] = d;
                invD[tid] = 1.f / d;
            }
            __syncthreads();  // invD visible; prev MMA done before H1 overwrite

            // fused: NS += e*PP(new token); H1 = relu(AP+BP+b1+NS*invD) -> hi/lo
#pragma unroll
            for (int it = 0; it < 5; it++) {
                int idx = tid + it * 512;
                int i = idx / 40, g = idx - i * 40, c0 = g * 4;
                int s = s0 + i;
                float e = eg[i + n - 1];
                float4 p = *(const float4*)(PP + (size_t)(s0 + i + n - 1) * LDO + c0);
                float4 ns = *(const float4*)(NS + i * 160 + c0);
                ns.x += e * p.x; ns.y += e * p.y;
                ns.z += e * p.z; ns.w += e * p.w;
                *(float4*)(NS + i * 160 + c0) = ns;

                float4 v = make_float4(0.f, 0.f, 0.f, 0.f);
                if (s < S) {
                    float4 a4 = *(const float4*)(AP + (size_t)s * LDO + c0);
                    float4 q4 = *(const float4*)(BP + (size_t)(s + n - 1) * LDO + c0);
                    float4 b4 = *(const float4*)(g_b1 + c0);
                    float id = invD[i];
                    v.x = fmaxf(a4.x + q4.x + b4.x + ns.x * id, 0.f);
                    v.y = fmaxf(a4.y + q4.y + b4.y + ns.y * id, 0.f);
                    v.z = fmaxf(a4.z + q4.z + b4.z + ns.z * id, 0.f);
                    v.w = fmaxf(a4.w + q4.w + b4.w + ns.w * id, 0.f);
                }
                unsigned short h[4], l[4];
                split_bf16(v.x, h[0], l[0]); split_bf16(v.y, h[1], l[1]);
                split_bf16(v.z, h[2], l[2]); split_bf16(v.w, h[3], l[3]);
                int cch = g >> 2, kk = (g & 3) * 4;
                unsigned short* dst = (unsigned short*)(H1s + (size_t)(cch * 64 + i) * 40 + kk);
                *(uint2*)dst        = make_uint2((unsigned)h[0] | ((unsigned)h[1] << 16),
                                                 (unsigned)h[2] | ((unsigned)h[3] << 16));
                *(uint2*)(dst + 16) = make_uint2((unsigned)l[0] | ((unsigned)l[1] << 16),
                                                 (unsigned)l[2] | ((unsigned)l[3] << 16));
            }
            __syncthreads();

            // MMA: W2 and H1 resident, 16-warp split, fused hi/lo B loads
            float acc[5][4];
#pragma unroll
            for (int t = 0; t < 5; t++)
#pragma unroll
                for (int j = 0; j < 4; j++) acc[t][j] = 0.f;
#pragma unroll
            for (int c = 0; c < 10; c++) {
                unsigned aBuf = h1Base + (unsigned)(c * 5120);
                unsigned bBuf = w2Base + (unsigned)(c * 12800);
                MMA_CHUNK_W(aBuf, bBuf);
            }

            // epilogue: relu(H2 + b2) . w3, reduce
            const int cBase = nw * 40 + 2 * (lane & 3);
            float s1 = 0.f, s2 = 0.f;
#pragma unroll
            for (int p = 0; p < 5; p++) {
                int col = cBase + p * 8;
                float2 w3 = *(const float2*)(g_w3 + col);
                float2 b2 = *(const float2*)(g_b2 + col);
                s1 += fmaxf(acc[p][0] + b2.x, 0.f) * w3.x + fmaxf(acc[p][1] + b2.y, 0.f) * w3.y;
                s2 += fmaxf(acc[p][2] + b2.x, 0.f) * w3.x + fmaxf(acc[p][3] + b2.y, 0.f) * w3.y;
            }
            s1 += __shfl_xor_sync(0xffffffffu, s1, 1);
            s1 += __shfl_xor_sync(0xffffffffu, s1, 2);
            s2 += __shfl_xor_sync(0xffffffffu, s2, 1);
            s2 += __shfl_xor_sync(0xffffffffu, s2, 2);
            if ((lane & 3) == 0) {
                int row = mw * 16 + (lane >> 2);
                red[row * 4 + nw]       = s1;
                red[(row + 8) * 4 + nw] = s2;
            }
            __syncthreads();

            if (tid < 64) {
                int s = s0 + tid;
                if (s < S) {
                    long long off = (long long)(n - 1) * (T_TOK + 1)
                                  - (long long)(n - 1) * n / 2;
                    out[off + s] = red[tid * 4] + red[tid * 4 + 1]
                                 + red[tid * 4 + 2] + red[tid * 4 + 3] + b3[0];
                }
            }
        }
        __syncthreads();
    }
}

// ---------------- host ----------------
extern "C" void kernel_launch(void* const* d_in, const int* in_sizes, int n_in,
                              void* d_out, int out_size)
{
    const float* embeds  = (const float*)d_in[0];
    const float* states  = (const float*)d_in[1];
    const float* attn_W1 = (const float*)d_in[2];
    const float* attn_b1 = (const float*)d_in[3];
    const float* attn_W2 = (const float*)d_in[4];
    const float* attn_b2 = (const float*)d_in[5];
    const float* attn_W3 = (const float*)d_in[6];
    const float* attn_b3 = (const float*)d_in[7];
    const float* sc_W1   = (const float*)d_in[8];
    const float* sc_b1   = (const float*)d_in[9];
    const float* sc_W2   = (const float*)d_in[10];
    const float* sc_b2   = (const float*)d_in[11];
    const float* sc_W3   = (const float*)d_in[12];
    const float* sc_b3   = (const float*)d_in[13];
    float* out = (float*)d_out;

    float *AH1, *AP, *BP, *PP, *LG;
    cudaGetSymbolAddress((void**)&AH1, g_AH1);
    cudaGetSymbolAddress((void**)&AP,  g_AP);
    cudaGetSymbolAddress((void**)&BP,  g_BP);
    cudaGetSymbolAddress((void**)&PP,  g_PP);
    cudaGetSymbolAddress((void**)&LG,  g_LG);

    const int gm128 = (T_TOK + 127) / 128;  // 157

    prep_all<<<148, 256>>>(attn_W1, sc_W1, attn_W2, sc_W2,
                           attn_b1, attn_b2, sc_b1, sc_b2, sc_W3, attn_W3);

    gemmA<<<dim3(gm128, 4), 512>>>(states, embeds, AH1, AP, BP, PP);

    attn2_k<<<gm128, 512>>>(AH1, attn_b3, LG);

    cudaFuncSetAttribute(span_k, cudaFuncAttributeMaxDynamicSharedMemorySize, SPAN_SMEM);
    span_k<<<148, 512, SPAN_SMEM>>>(AP, BP, PP, LG, sc_b3, out);
}

// round 11
// speedup vs baseline: 1.5266x; 1.5266x over previous
#include <cuda_runtime.h>
#include <cuda_bf16.h>

#define T_TOK 20000
#define LDO   160

// ---------------- scratch ----------------
__device__ __align__(256) float g_AP [T_TOK * LDO];
__device__ __align__(256) float g_BP [T_TOK * LDO];
__device__ __align__(256) float g_PP [(T_TOK + 64) * LDO];  // 64 zero pad rows
__device__ __align__(256) float g_LG [T_TOK];
__device__ int g_ctr;
__device__ unsigned g_maxbits;

// weight images: per k16-chunk: 160 rows(n) x 40 bf16 (16 hi | 16 lo | 8 pad)
#define CH_ELEMS 6400
#define O_A1 0
#define O_SA (25 * CH_ELEMS)
#define O_SB (50 * CH_ELEMS)
#define O_SP (75 * CH_ELEMS)
#define O_A2 (94 * CH_ELEMS)
#define O_W2 (104 * CH_ELEMS)
__device__ __align__(256) __nv_bfloat16 g_Wimg[114 * CH_ELEMS];

__device__ __align__(256) float g_ba1[160];
__device__ __align__(256) float g_ba2[160];
__device__ __align__(256) float g_b1 [160];
__device__ __align__(256) float g_b2 [160];
__device__ __align__(256) float g_w3 [160];
__device__ __align__(256) float g_wa3[160];

// ---------------- helpers ----------------
__device__ __forceinline__ unsigned cvta_s(const void* p) {
    return (unsigned)__cvta_generic_to_shared(p);
}
__device__ __forceinline__ void ldmx4(unsigned* r, unsigned addr) {
    asm volatile("ldmatrix.sync.aligned.m8n8.x4.shared.b16 {%0,%1,%2,%3}, [%4];"
        : "=r"(r[0]), "=r"(r[1]), "=r"(r[2]), "=r"(r[3]) : "r"(addr));
}
__device__ __forceinline__ void mma16816(float* d, const unsigned* a, const unsigned* b) {
    asm volatile(
        "mma.sync.aligned.m16n8k16.row.col.f32.bf16.bf16.f32 "
        "{%0,%1,%2,%3}, {%4,%5,%6,%7}, {%8,%9}, {%0,%1,%2,%3};"
        : "+f"(d[0]), "+f"(d[1]), "+f"(d[2]), "+f"(d[3])
        : "r"(a[0]), "r"(a[1]), "r"(a[2]), "r"(a[3]), "r"(b[0]), "r"(b[1]));
}
__device__ __forceinline__ void split_bf16(float v, unsigned short& h, unsigned short& l) {
    __nv_bfloat16 hb = __float2bfloat16_rn(v);
    __nv_bfloat16 lb = __float2bfloat16_rn(v - __bfloat162float(hb));
    h = __bfloat16_as_ushort(hb);
    l = __bfloat16_as_ushort(lb);
}
__device__ __forceinline__ unsigned encf(float x) {
    unsigned u = __float_as_uint(x);
    return (u & 0x80000000u) ? ~u : (u | 0x80000000u);
}
__device__ __forceinline__ float decf(unsigned u) {
    unsigned b = (u & 0x80000000u) ? (u & 0x7fffffffu) : ~u;
    return __uint_as_float(b);
}

// ---------------- single fused prep ----------------
__global__ void prep_all(const float* __restrict__ aW1, const float* __restrict__ scW1,
                         const float* __restrict__ aW2, const float* __restrict__ scW2,
                         const float* __restrict__ ab1, const float* __restrict__ ab2,
                         const float* __restrict__ sb1, const float* __restrict__ sb2,
                         const float* __restrict__ sW3, const float* __restrict__ aW3)
{
    int tid = threadIdx.x;
    if (blockIdx.x == 0) {
        if (tid < 160) {
            bool ok = tid < 150;
            g_ba1[tid] = ok ? ab1[tid] : 0.f;
            g_ba2[tid] = ok ? ab2[tid] : 0.f;
            g_b1 [tid] = ok ? sb1[tid] : 0.f;
            g_b2 [tid] = ok ? sb2[tid] : 0.f;
            g_w3 [tid] = ok ? sW3[tid] : 0.f;
            g_wa3[tid] = ok ? aW3[tid] : 0.f;
        }
        if (tid == 0) { g_ctr = 0; g_maxbits = 0u; }
    }
    const int total = 114 * 2560;
    for (int idx = blockIdx.x * blockDim.x + tid; idx < total;
         idx += gridDim.x * blockDim.x) {
        int c   = idx / 2560;
        int rem = idx - c * 2560;
        int nn  = rem >> 4;
        int kk  = rem & 15;
        const float* W; int K; int lc;
        if      (c < 25)  { W = aW1;             K = 400; lc = c;       }
        else if (c < 50)  { W = scW1;            K = 400; lc = c - 25;  }
        else if (c < 75)  { W = scW1 + 400*150;  K = 400; lc = c - 50;  }
        else if (c < 94)  { W = scW1 + 800*150;  K = 300; lc = c - 75;  }
        else if (c < 104) { W = aW2;             K = 150; lc = c - 94;  }
        else              { W = scW2;            K = 150; lc = c - 104; }
        int k = lc * 16 + kk;
        float v = (k < K && nn < 150) ? W[k * 150 + nn] : 0.f;
        unsigned short h, l;
        split_bf16(v, h, l);
        unsigned short* dst = (unsigned short*)(g_Wimg + (size_t)c * CH_ELEMS + nn * 40);
        dst[kk]      = h;
        dst[16 + kk] = l;
        if (kk < 8) dst[32 + kk] = 0;
    }
}

// ---------------- staging (512 threads, 128-row tiles) ----------------
__device__ __forceinline__ void stage_A128(const float* __restrict__ X, int ldx,
                                           int Kreal, int m0, int M, int c,
                                           __nv_bfloat16* __restrict__ Abuf, int tid)
{
    int r  = tid >> 2;
    int kq = tid & 3;
    int m  = m0 + r;
    int k0 = c * 16 + kq * 4;
    float4 v = make_float4(0.f, 0.f, 0.f, 0.f);
    if (m < M) {
        if (k0 + 3 < Kreal) {
            v = *(const float4*)(X + (size_t)m * ldx + k0);
        } else {
            float* pv = (float*)&v;
            for (int j = 0; j < 4; j++)
                if (k0 + j < Kreal) pv[j] = X[(size_t)m * ldx + k0 + j];
        }
    }
    unsigned short h[4], l[4];
    split_bf16(v.x, h[0], l[0]); split_bf16(v.y, h[1], l[1]);
    split_bf16(v.z, h[2], l[2]); split_bf16(v.w, h[3], l[3]);
    unsigned short* dst = (unsigned short*)(Abuf + r * 40 + kq * 4);
    *(uint2*)dst        = make_uint2((unsigned)h[0] | ((unsigned)h[1] << 16),
                                     (unsigned)h[2] | ((unsigned)h[3] << 16));
    *(uint2*)(dst + 16) = make_uint2((unsigned)l[0] | ((unsigned)l[1] << 16),
                                     (unsigned)l[2] | ((unsigned)l[3] << 16));
}

__device__ __forceinline__ void stage_B512(const __nv_bfloat16* __restrict__ img, int c,
                                           __nv_bfloat16* __restrict__ Bbuf, int tid)
{
    const float4* src = (const float4*)(img + (size_t)c * CH_ELEMS);
    float4* dst = (float4*)Bbuf;
    for (int i = tid; i < 800; i += 512) dst[i] = src[i];
}

// ---------------- core MMA macro (16 rows x 80 cols per warp) ----------------
#define MMA_CHUNK(aBuf, bBuf)                                                   \
    {                                                                           \
        unsigned ah[4], al[4];                                                  \
        ldmx4(ah, (aBuf) + aOff);                                               \
        ldmx4(al, (aBuf) + aOff + 32);                                          \
        _Pragma("unroll")                                                       \
        for (int p = 0; p < 5; p++) {                                           \
            unsigned bh[4], bl[4];                                              \
            unsigned baddr = (bBuf) + (unsigned)((nw * 80 + p * 16) * 80) + bOff; \
            ldmx4(bh, baddr);                                                   \
            ldmx4(bl, baddr + 32);                                              \
            mma16816(acc[2 * p],     ah, bh);                                   \
            mma16816(acc[2 * p],     ah, bl);                                   \
            mma16816(acc[2 * p],     al, bh);                                   \
            mma16816(acc[2 * p + 1], ah, bh + 2);                               \
            mma16816(acc[2 * p + 1], ah, bl + 2);                               \
            mma16816(acc[2 * p + 1], al, bh + 2);                               \
        }                                                                       \
    }

// span 16-warp layout: 16 rows x 40 cols, hi+lo B fused in one ldmatrix.x4
#define MMA_CHUNK_W(aBuf, bBuf)                                                 \
    {                                                                           \
        unsigned ah[4], al[4];                                                  \
        ldmx4(ah, (aBuf) + aOff);                                               \
        ldmx4(al, (aBuf) + aOff + 32);                                          \
        _Pragma("unroll")                                                       \
        for (int p = 0; p < 5; p++) {                                           \
            unsigned bb[4];                                                     \
            unsigned baddr = (bBuf) + (unsigned)((nw * 40 + p * 8) * 80) + bOff4; \
            ldmx4(bb, baddr);                                                   \
            mma16816(acc[p], ah, bb);                                           \
            mma16816(acc[p], ah, bb + 2);                                       \
            mma16816(acc[p], al, bb);                                           \
        }                                                                       \
    }

// ---------------- batched GEMM: 4 jobs; job 0 fuses attn layer2 + logits ----------------
// dyn smem: As 20480 @0, Bs 25600 @20480, H1big 102400 @46080 -> 148480
#define GEMMA_SMEM 148480

__global__ __launch_bounds__(512, 1) void gemmA(
    const float* __restrict__ states, const float* __restrict__ embeds,
    float* __restrict__ AP, float* __restrict__ BP,
    float* __restrict__ PP, float* __restrict__ LG,
    const float* __restrict__ ab3)
{
    extern __shared__ char smc[];
    __nv_bfloat16* As    = (__nv_bfloat16*)smc;
    __nv_bfloat16* Bs    = (__nv_bfloat16*)(smc + 20480);
    __nv_bfloat16* H1big = (__nv_bfloat16*)(smc + 46080);
    __shared__ float red2[256];
    __shared__ float bmax[4];

    const float* X; int ldx, Kreal, chunks; const __nv_bfloat16* img;
    float* Y;
    switch (blockIdx.y) {
        case 0: X = states; ldx = 400; Kreal = 400; chunks = 25;
                img = g_Wimg + O_A1; Y = nullptr; break;          // fused attn path
        case 1: X = states; ldx = 400; Kreal = 400; chunks = 25;
                img = g_Wimg + O_SA; Y = AP; break;
        case 2: X = states; ldx = 400; Kreal = 400; chunks = 25;
                img = g_Wimg + O_SB; Y = BP; break;
        default: X = embeds; ldx = 300; Kreal = 300; chunks = 19;
                img = g_Wimg + O_SP; Y = PP; break;
    }
    const int M = T_TOK;
    const int tid  = threadIdx.x;
    const int lane = tid & 31;
    const int warp = tid >> 5;
    const int mw   = warp & 7;
    const int nw   = warp >> 3;
    const int m0   = blockIdx.x * 128;

    float acc[10][4];
#pragma unroll
    for (int t = 0; t < 10; t++)
#pragma unroll
        for (int j = 0; j < 4; j++) acc[t][j] = 0.f;

    const int aRow = (lane & 7) + ((lane & 8) ? 8 : 0);
    const unsigned aOff = (unsigned)((mw * 16 + aRow) * 80 + ((lane & 16) ? 16 : 0));
    const int bRow = (lane & 7) + ((lane & 16) ? 8 : 0);
    const unsigned bOff = (unsigned)(bRow * 80 + ((lane & 8) ? 16 : 0));
    const unsigned asBase = cvta_s(As);
    const unsigned bsBase = cvta_s(Bs);

    stage_A128(X, ldx, Kreal, m0, M, 0, As, tid);
    stage_B512(img, 0, Bs, tid);
    __syncthreads();

    for (int c = 0; c < chunks; c++) {
        int cur = c & 1;
        if (c + 1 < chunks) {
            stage_A128(X, ldx, Kreal, m0, M, c + 1, As + (cur ^ 1) * 5120, tid);
            stage_B512(img, c + 1, Bs + (cur ^ 1) * 6400, tid);
        }
        unsigned aBuf = asBase + cur * 10240;
        unsigned bBuf = bsBase + cur * 12800;
        MMA_CHUNK(aBuf, bBuf);
        __syncthreads();
    }

    const int rloc  = mw * 16 + (lane >> 2);  // local row 0..127
    const int cBase = nw * 80 + 2 * (lane & 3);

    if (blockIdx.y != 0) {
        // plain epilogue (no bias, no relu) for AP/BP/PP
        const int r1 = m0 + rloc;
#pragma unroll
        for (int t = 0; t < 10; t++) {
            int col = cBase + t * 8;
            float2 vA = make_float2(acc[t][0], acc[t][1]);
            float2 vB = make_float2(acc[t][2], acc[t][3]);
            if (r1 < M)     *(float2*)(Y + (size_t)r1 * LDO + col)       = vA;
            if (r1 + 8 < M) *(float2*)(Y + (size_t)(r1 + 8) * LDO + col) = vB;
        }
        return;
    }

    // ===== job 0: fused attention layer-2 + logits =====
    // 1. H1 = relu(acc + ba1) -> split bf16 -> H1big (MMA-A chunk layout)
#pragma unroll
    for (int t = 0; t < 10; t++) {
        int col = cBase + t * 8;
        float b0 = g_ba1[col], b1v = g_ba1[col + 1];
        float vA0 = fmaxf(acc[t][0] + b0,  0.f);
        float vA1 = fmaxf(acc[t][1] + b1v, 0.f);
        float vB0 = fmaxf(acc[t][2] + b0,  0.f);
        float vB1 = fmaxf(acc[t][3] + b1v, 0.f);
        int cch = col >> 4, kk = col & 15;
        unsigned short h, l;
        unsigned short* rowA = (unsigned short*)(H1big + (size_t)(cch * 128 + rloc) * 40);
        unsigned short* rowB = (unsigned short*)(H1big + (size_t)(cch * 128 + rloc + 8) * 40);
        split_bf16(vA0, h, l); rowA[kk] = h;     rowA[16 + kk] = l;
        split_bf16(vA1, h, l); rowA[kk + 1] = h; rowA[17 + kk] = l;
        split_bf16(vB0, h, l); rowB[kk] = h;     rowB[16 + kk] = l;
        split_bf16(vB1, h, l); rowB[kk + 1] = h; rowB[17 + kk] = l;
    }
    // zero the 8-pad tail of each H1big row (ldmatrix never reads it, but be safe)
    __syncthreads();

    // 2. second MMA: logitsH2 = H1 @ attn_W2 (A2 image), A resident in H1big
    const unsigned h1bigBase = cvta_s(H1big);
#pragma unroll
    for (int t = 0; t < 10; t++)
#pragma unroll
        for (int j = 0; j < 4; j++) acc[t][j] = 0.f;

    stage_B512(g_Wimg + O_A2, 0, Bs, tid);
    __syncthreads();
    for (int c = 0; c < 10; c++) {
        int cur = c & 1;
        if (c + 1 < 10) stage_B512(g_Wimg + O_A2, c + 1, Bs + (cur ^ 1) * 6400, tid);
        unsigned aBuf = h1bigBase + (unsigned)(c * 10240);
        unsigned bBuf = bsBase + cur * 12800;
        MMA_CHUNK(aBuf, bBuf);
        __syncthreads();
    }

    // 3. logits = relu(H2 + ba2) . wa3, reduce, global max
    float s1 = 0.f, s2 = 0.f;
#pragma unroll
    for (int t = 0; t < 10; t++) {
        int col = cBase + t * 8;
        float2 b2 = *(const float2*)(g_ba2 + col);
        float2 w3 = *(const float2*)(g_wa3 + col);
        s1 += fmaxf(acc[t][0] + b2.x, 0.f) * w3.x + fmaxf(acc[t][1] + b2.y, 0.f) * w3.y;
        s2 += fmaxf(acc[t][2] + b2.x, 0.f) * w3.x + fmaxf(acc[t][3] + b2.y, 0.f) * w3.y;
    }
    s1 += __shfl_xor_sync(0xffffffffu, s1, 1);
    s1 += __shfl_xor_sync(0xffffffffu, s1, 2);
    s2 += __shfl_xor_sync(0xffffffffu, s2, 1);
    s2 += __shfl_xor_sync(0xffffffffu, s2, 2);
    if ((lane & 3) == 0) {
        red2[rloc * 2 + nw]       = s1;
        red2[(rloc + 8) * 2 + nw] = s2;
    }
    __syncthreads();
    if (tid < 128) {
        int m = m0 + tid;
        float v = red2[tid * 2] + red2[tid * 2 + 1] + ab3[0];
        float mv = -3.4e38f;
        if (m < M) { LG[m] = v; mv = v; }
#pragma unroll
        for (int o = 16; o; o >>= 1) mv = fmaxf(mv, __shfl_xor_sync(0xffffffffu, mv, o));
        if ((tid & 31) == 0) bmax[tid >> 5] = mv;
    }
    __syncthreads();
    if (tid == 0)
        atomicMax(&g_maxbits, encf(fmaxf(fmaxf(bmax[0], bmax[1]),
                                         fmaxf(bmax[2], bmax[3]))));
}

// ---------------- persistent span kernel (R9 version) ----------------
// smem: W2s 128000 @0, H1s 51200 @128000, NS 40960 @179200, eg 320 @220160,
//       sD 256 @220480, invD 256 @220736, red 1024 @220992 -> 222016
#define SPAN_SMEM 222016
#define N_UNITS (313 * 3)

__global__ __launch_bounds__(512, 1) void span_k(
    const float* __restrict__ AP, const float* __restrict__ BP,
    const float* __restrict__ PP, const float* __restrict__ LG,
    const float* __restrict__ b3, float* __restrict__ out)
{
    extern __shared__ char sm[];
    __nv_bfloat16* W2s = (__nv_bfloat16*)sm;
    __nv_bfloat16* H1s = (__nv_bfloat16*)(sm + 128000);
    float* NS   = (float*)(sm + 179200);
    float* eg   = (float*)(sm + 220160);
    float* sD   = (float*)(sm + 220480);
    float* invD = (float*)(sm + 220736);
    float* red  = (float*)(sm + 220992);
    __shared__ int s_u;

    const int tid  = threadIdx.x;
    const int lane = tid & 31;
    const int warp = tid >> 5;
    const int mw   = warp & 3;   // 16-row group
    const int nw   = warp >> 2;  // 40-col group (0..3)

    const int aRow = (lane & 7) + ((lane & 8) ? 8 : 0);
    const unsigned aOff = (unsigned)((mw * 16 + aRow) * 80 + ((lane & 16) ? 16 : 0));
    const unsigned bOff4 = (unsigned)((lane & 7) * 80 + (((lane >> 3) & 3) * 16));
    const unsigned h1Base = cvta_s(H1s);
    const unsigned w2Base = cvta_s(W2s);

    // load full W2 image (128 KB) once
    {
        const float4* src = (const float4*)(g_Wimg + O_W2);
        float4* dst = (float4*)W2s;
        for (int i = tid; i < 8000; i += 512) dst[i] = src[i];
    }

    const float Mx = decf(g_maxbits);

    while (true) {
        if (tid == 0) s_u = atomicAdd(&g_ctr, 1);
        __syncthreads();
        int u = s_u;
        if (u >= N_UNITS) break;
        int tile = u / 3;
        int grp  = u - tile * 3;
        int s0 = tile * 64;
        int n0   = (grp == 0) ? 1 : (grp == 1 ? 5 : 8);
        int nend = (grp == 0) ? 5 : (grp == 1 ? 8 : 11);

        if (tid < 80) {
            int t = s0 + tid;
            eg[tid] = (t < T_TOK) ? __expf(LG[t] - Mx) : 0.f;
        }
        __syncthreads();

        // init NS (numerator for width n0) and sD/invD
#pragma unroll
        for (int it = 0; it < 5; it++) {
            int idx = tid + it * 512;
            int i = idx / 40, g = idx - i * 40, c0 = g * 4;
            float4 a = make_float4(0.f, 0.f, 0.f, 0.f);
            for (int j = 0; j < n0; j++) {
                float e = eg[i + j];
                float4 p = *(const float4*)(PP + (size_t)(s0 + i + j) * LDO + c0);
                a.x += e * p.x; a.y += e * p.y;
                a.z += e * p.z; a.w += e * p.w;
            }
            *(float4*)(NS + i * 160 + c0) = a;
        }
        if (tid < 64) {
            float d = 0.f;
            for (int j = 0; j < n0; j++) d += eg[tid + j];
            sD[tid] = d;
            invD[tid] = 1.f / d;
        }
        __syncthreads();

        for (int n = n0; n < nend; n++) {
            const int S = T_TOK - n + 1;

            // build H1 = relu(AP[s] + BP[s+n-1] + b1 + NS*invD) -> hi/lo split
#pragma unroll
            for (int it = 0; it < 5; it++) {
                int idx = tid + it * 512;
                int i = idx / 40, g = idx - i * 40, c0 = g * 4;
                int s = s0 + i;
                float4 v = make_float4(0.f, 0.f, 0.f, 0.f);
                if (s < S) {
                    float4 a4 = *(const float4*)(AP + (size_t)s * LDO + c0);
                    float4 q4 = *(const float4*)(BP + (size_t)(s + n - 1) * LDO + c0);
                    float4 b4 = *(const float4*)(g_b1 + c0);
                    float4 ns = *(const float4*)(NS + i * 160 + c0);
                    float id = invD[i];
                    v.x = fmaxf(a4.x + q4.x + b4.x + ns.x * id, 0.f);
                    v.y = fmaxf(a4.y + q4.y + b4.y + ns.y * id, 0.f);
                    v.z = fmaxf(a4.z + q4.z + b4.z + ns.z * id, 0.f);
                    v.w = fmaxf(a4.w + q4.w + b4.w + ns.w * id, 0.f);
                }
                unsigned short h[4], l[4];
                split_bf16(v.x, h[0], l[0]); split_bf16(v.y, h[1], l[1]);
                split_bf16(v.z, h[2], l[2]); split_bf16(v.w, h[3], l[3]);
                int cch = g >> 2, kk = (g & 3) * 4;
                unsigned short* dst = (unsigned short*)(H1s + (size_t)(cch * 64 + i) * 40 + kk);
                *(uint2*)dst        = make_uint2((unsigned)h[0] | ((unsigned)h[1] << 16),
                                                 (unsigned)h[2] | ((unsigned)h[3] << 16));
                *(uint2*)(dst + 16) = make_uint2((unsigned)l[0] | ((unsigned)l[1] << 16),
                                                 (unsigned)l[2] | ((unsigned)l[3] << 16));
            }
            __syncthreads();

            // MMA: W2 and H1 resident, 16-warp split, fused hi/lo B loads
            float acc[5][4];
#pragma unroll
            for (int t = 0; t < 5; t++)
#pragma unroll
                for (int j = 0; j < 4; j++) acc[t][j] = 0.f;
#pragma unroll
            for (int c = 0; c < 10; c++) {
                unsigned aBuf = h1Base + (unsigned)(c * 5120);
                unsigned bBuf = w2Base + (unsigned)(c * 12800);
                MMA_CHUNK_W(aBuf, bBuf);
            }

            // epilogue: relu(H2 + b2) . w3, reduce
            const int cBase = nw * 40 + 2 * (lane & 3);
            float s1 = 0.f, s2 = 0.f;
#pragma unroll
            for (int p = 0; p < 5; p++) {
                int col = cBase + p * 8;
                float2 w3 = *(const float2*)(g_w3 + col);
                float2 b2 = *(const float2*)(g_b2 + col);
                s1 += fmaxf(acc[p][0] + b2.x, 0.f) * w3.x + fmaxf(acc[p][1] + b2.y, 0.f) * w3.y;
                s2 += fmaxf(acc[p][2] + b2.x, 0.f) * w3.x + fmaxf(acc[p][3] + b2.y, 0.f) * w3.y;
            }
            s1 += __shfl_xor_sync(0xffffffffu, s1, 1);
            s1 += __shfl_xor_sync(0xffffffffu, s1, 2);
            s2 += __shfl_xor_sync(0xffffffffu, s2, 1);
            s2 += __shfl_xor_sync(0xffffffffu, s2, 2);
            if ((lane & 3) == 0) {
                int row = mw * 16 + (lane >> 2);
                red[row * 4 + nw]       = s1;
                red[(row + 8) * 4 + nw] = s2;
            }
            __syncthreads();

            if (tid < 64) {
                int s = s0 + tid;
                if (s < S) {
                    long long off = (long long)(n - 1) * (T_TOK + 1)
                                  - (long long)(n - 1) * n / 2;
                    out[off + s] = red[tid * 4] + red[tid * 4 + 1]
                                 + red[tid * 4 + 2] + red[tid * 4 + 3] + b3[0];
                }
            }

            // incremental update for next width
            if (n + 1 < nend) {
#pragma unroll
                for (int it = 0; it < 5; it++) {
                    int idx = tid + it * 512;
                    int i = idx / 40, g = idx - i * 40, c0 = g * 4;
                    float e = eg[i + n];
                    float4 p = *(const float4*)(PP + (size_t)(s0 + i + n) * LDO + c0);
                    float4 ns = *(const float4*)(NS + i * 160 + c0);
                    ns.x += e * p.x; ns.y += e * p.y;
                    ns.z += e * p.z; ns.w += e * p.w;
                    *(float4*)(NS + i * 160 + c0) = ns;
                }
                if (tid < 64) {
                    sD[tid] += eg[tid + n];
                    invD[tid] = 1.f / sD[tid];
                }
            }
            __syncthreads();
        }
    }
}

// ---------------- host ----------------
extern "C" void kernel_launch(void* const* d_in, const int* in_sizes, int n_in,
                              void* d_out, int out_size)
{
    const float* embeds  = (const float*)d_in[0];
    const float* states  = (const float*)d_in[1];
    const float* attn_W1 = (const float*)d_in[2];
    const float* attn_b1 = (const float*)d_in[3];
    const float* attn_W2 = (const float*)d_in[4];
    const float* attn_b2 = (const float*)d_in[5];
    const float* attn_W3 = (const float*)d_in[6];
    const float* attn_b3 = (const float*)d_in[7];
    const float* sc_W1   = (const float*)d_in[8];
    const float* sc_b1   = (const float*)d_in[9];
    const float* sc_W2   = (const float*)d_in[10];
    const float* sc_b2   = (const float*)d_in[11];
    const float* sc_W3   = (const float*)d_in[12];
    const float* sc_b3   = (const float*)d_in[13];
    float* out = (float*)d_out;

    float *AP, *BP, *PP, *LG;
    cudaGetSymbolAddress((void**)&AP,  g_AP);
    cudaGetSymbolAddress((void**)&BP,  g_BP);
    cudaGetSymbolAddress((void**)&PP,  g_PP);
    cudaGetSymbolAddress((void**)&LG,  g_LG);

    const int gm128 = (T_TOK + 127) / 128;  // 157

    prep_all<<<148, 256>>>(attn_W1, sc_W1, attn_W2, sc_W2,
                           attn_b1, attn_b2, sc_b1, sc_b2, sc_W3, attn_W3);

    cudaFuncSetAttribute(gemmA, cudaFuncAttributeMaxDynamicSharedMemorySize, GEMMA_SMEM);
    gemmA<<<dim3(gm128, 4), 512, GEMMA_SMEM>>>(states, embeds, AP, BP, PP, LG, attn_b3);

    cudaFuncSetAttribute(span_k, cudaFuncAttributeMaxDynamicSharedMemorySize, SPAN_SMEM);
    span_k<<<148, 512, SPAN_SMEM>>>(AP, BP, PP, LG, sc_b3, out);
}

// round 14
// speedup vs baseline: 1.6313x; 1.0686x over previous
#include <cuda_runtime.h>
#include <cuda_bf16.h>

#define T_TOK 20000
#define LDO   160

// ---------------- scratch ----------------
__device__ __align__(256) float g_AP [T_TOK * LDO];
__device__ __align__(256) float g_BP [T_TOK * LDO];
__device__ __align__(256) float g_PP [(T_TOK + 64) * LDO];  // 64 zero pad rows
__device__ __align__(256) float g_LG [T_TOK];
__device__ int g_ctr;
__device__ unsigned g_maxbits;

// weight images: per k16-chunk: 160 rows(n) x 40 bf16 (16 hi | 16 lo | 8 pad)
#define CH_ELEMS 6400
#define O_A1 0
#define O_SA (25 * CH_ELEMS)
#define O_SB (50 * CH_ELEMS)
#define O_SP (75 * CH_ELEMS)
#define O_A2 (94 * CH_ELEMS)
#define O_W2 (104 * CH_ELEMS)
__device__ __align__(256) __nv_bfloat16 g_Wimg[114 * CH_ELEMS];

__device__ __align__(256) float g_ba1[160];
__device__ __align__(256) float g_ba2[160];
__device__ __align__(256) float g_b1 [160];
__device__ __align__(256) float g_b2 [160];
__device__ __align__(256) float g_w3 [160];
__device__ __align__(256) float g_wa3[160];

// ---------------- helpers ----------------
__device__ __forceinline__ unsigned cvta_s(const void* p) {
    return (unsigned)__cvta_generic_to_shared(p);
}
__device__ __forceinline__ void ldmx4(unsigned* r, unsigned addr) {
    asm volatile("ldmatrix.sync.aligned.m8n8.x4.shared.b16 {%0,%1,%2,%3}, [%4];"
        : "=r"(r[0]), "=r"(r[1]), "=r"(r[2]), "=r"(r[3]) : "r"(addr));
}
__device__ __forceinline__ void mma16816(float* d, const unsigned* a, const unsigned* b) {
    asm volatile(
        "mma.sync.aligned.m16n8k16.row.col.f32.bf16.bf16.f32 "
        "{%0,%1,%2,%3}, {%4,%5,%6,%7}, {%8,%9}, {%0,%1,%2,%3};"
        : "+f"(d[0]), "+f"(d[1]), "+f"(d[2]), "+f"(d[3])
        : "r"(a[0]), "r"(a[1]), "r"(a[2]), "r"(a[3]), "r"(b[0]), "r"(b[1]));
}
__device__ __forceinline__ void split_bf16(float v, unsigned short& h, unsigned short& l) {
    __nv_bfloat16 hb = __float2bfloat16_rn(v);
    __nv_bfloat16 lb = __float2bfloat16_rn(v - __bfloat162float(hb));
    h = __bfloat16_as_ushort(hb);
    l = __bfloat16_as_ushort(lb);
}
__device__ __forceinline__ unsigned encf(float x) {
    unsigned u = __float_as_uint(x);
    return (u & 0x80000000u) ? ~u : (u | 0x80000000u);
}
__device__ __forceinline__ float decf(unsigned u) {
    unsigned b = (u & 0x80000000u) ? (u & 0x7fffffffu) : ~u;
    return __uint_as_float(b);
}
__device__ __forceinline__ void cp_async16(unsigned saddr, const void* gsrc) {
    asm volatile("cp.async.cg.shared.global [%0], [%1], 16;"
        :: "r"(saddr), "l"(gsrc));
}
#define CP_COMMIT   asm volatile("cp.async.commit_group;" ::: "memory")
#define CP_WAIT_ALL asm volatile("cp.async.wait_group 0;" ::: "memory")

// ---------------- single fused prep ----------------
__global__ void prep_all(const float* __restrict__ aW1, const float* __restrict__ scW1,
                         const float* __restrict__ aW2, const float* __restrict__ scW2,
                         const float* __restrict__ ab1, const float* __restrict__ ab2,
                         const float* __restrict__ sb1, const float* __restrict__ sb2,
                         const float* __restrict__ sW3, const float* __restrict__ aW3)
{
    int tid = threadIdx.x;
    if (blockIdx.x == 0) {
        if (tid < 160) {
            bool ok = tid < 150;
            g_ba1[tid] = ok ? ab1[tid] : 0.f;
            g_ba2[tid] = ok ? ab2[tid] : 0.f;
            g_b1 [tid] = ok ? sb1[tid] : 0.f;
            g_b2 [tid] = ok ? sb2[tid] : 0.f;
            g_w3 [tid] = ok ? sW3[tid] : 0.f;
            g_wa3[tid] = ok ? aW3[tid] : 0.f;
        }
        if (tid == 0) { g_ctr = 0; g_maxbits = 0u; }
    }
    const int total = 114 * 2560;
    for (int idx = blockIdx.x * blockDim.x + tid; idx < total;
         idx += gridDim.x * blockDim.x) {
        int c   = idx / 2560;
        int rem = idx - c * 2560;
        int nn  = rem >> 4;
        int kk  = rem & 15;
        const float* W; int K; int lc;
        if      (c < 25)  { W = aW1;             K = 400; lc = c;       }
        else if (c < 50)  { W = scW1;            K = 400; lc = c - 25;  }
        else if (c < 75)  { W = scW1 + 400*150;  K = 400; lc = c - 50;  }
        else if (c < 94)  { W = scW1 + 800*150;  K = 300; lc = c - 75;  }
        else if (c < 104) { W = aW2;             K = 150; lc = c - 94;  }
        else              { W = scW2;            K = 150; lc = c - 104; }
        int k = lc * 16 + kk;
        float v = (k < K && nn < 150) ? W[k * 150 + nn] : 0.f;
        unsigned short h, l;
        split_bf16(v, h, l);
        unsigned short* dst = (unsigned short*)(g_Wimg + (size_t)c * CH_ELEMS + nn * 40);
        dst[kk]      = h;
        dst[16 + kk] = l;
        if (kk < 8) dst[32 + kk] = 0;
    }
}

// ---------------- staging (512 threads, 128-row tiles) ----------------
__device__ __forceinline__ void stage_A128(const float* __restrict__ X, int ldx,
                                           int Kreal, int m0, int M, int c,
                                           __nv_bfloat16* __restrict__ Abuf, int tid)
{
    int r  = tid >> 2;
    int kq = tid & 3;
    int m  = m0 + r;
    int k0 = c * 16 + kq * 4;
    float4 v = make_float4(0.f, 0.f, 0.f, 0.f);
    if (m < M) {
        if (k0 + 3 < Kreal) {
            v = *(const float4*)(X + (size_t)m * ldx + k0);
        } else {
            float* pv = (float*)&v;
            for (int j = 0; j < 4; j++)
                if (k0 + j < Kreal) pv[j] = X[(size_t)m * ldx + k0 + j];
        }
    }
    unsigned short h[4], l[4];
    split_bf16(v.x, h[0], l[0]); split_bf16(v.y, h[1], l[1]);
    split_bf16(v.z, h[2], l[2]); split_bf16(v.w, h[3], l[3]);
    unsigned short* dst = (unsigned short*)(Abuf + r * 40 + kq * 4);
    *(uint2*)dst        = make_uint2((unsigned)h[0] | ((unsigned)h[1] << 16),
                                     (unsigned)h[2] | ((unsigned)h[3] << 16));
    *(uint2*)(dst + 16) = make_uint2((unsigned)l[0] | ((unsigned)l[1] << 16),
                                     (unsigned)l[2] | ((unsigned)l[3] << 16));
}

// async B-chunk copy: 160x40 bf16 = 800x16B via cp.async (caller commits/waits)
__device__ __forceinline__ void stage_B_async(const __nv_bfloat16* __restrict__ img, int c,
                                              __nv_bfloat16* __restrict__ Bbuf, int tid)
{
    const char* src = (const char*)(img + (size_t)c * CH_ELEMS);
    unsigned dst = cvta_s(Bbuf);
    for (int i = tid; i < 800; i += 512)
        cp_async16(dst + i * 16, src + i * 16);
}

__device__ __forceinline__ void stage_B512(const __nv_bfloat16* __restrict__ img, int c,
                                           __nv_bfloat16* __restrict__ Bbuf, int tid)
{
    const float4* src = (const float4*)(img + (size_t)c * CH_ELEMS);
    float4* dst = (float4*)Bbuf;
    for (int i = tid; i < 800; i += 512) dst[i] = src[i];
}

// ---------------- core MMA macro (16 rows x 80 cols per warp, 80B rows) ----------------
#define MMA_CHUNK(aBuf, bBuf)                                                   \
    {                                                                           \
        unsigned ah[4], al[4];                                                  \
        ldmx4(ah, (aBuf) + aOff);                                               \
        ldmx4(al, (aBuf) + aOff + 32);                                          \
        _Pragma("unroll")                                                       \
        for (int p = 0; p < 5; p++) {                                           \
            unsigned bh[4], bl[4];                                              \
            unsigned baddr = (bBuf) + (unsigned)((nw * 80 + p * 16) * 80) + bOff; \
            ldmx4(bh, baddr);                                                   \
            ldmx4(bl, baddr + 32);                                              \
            mma16816(acc[2 * p],     ah, bh);                                   \
            mma16816(acc[2 * p],     ah, bl);                                   \
            mma16816(acc[2 * p],     al, bh);                                   \
            mma16816(acc[2 * p + 1], ah, bh + 2);                               \
            mma16816(acc[2 * p + 1], ah, bl + 2);                               \
            mma16816(acc[2 * p + 1], al, bh + 2);                               \
        }                                                                       \
    }

// span 16-warp layout: 16 rows x 40 cols, hi+lo B fused in one ldmatrix.x4
#define MMA_CHUNK_W(aBuf, bBuf)                                                 \
    {                                                                           \
        unsigned ah[4], al[4];                                                  \
        ldmx4(ah, (aBuf) + aOff);                                               \
        ldmx4(al, (aBuf) + aOff + 32);                                          \
        _Pragma("unroll")                                                       \
        for (int p = 0; p < 5; p++) {                                           \
            unsigned bb[4];                                                     \
            unsigned baddr = (bBuf) + (unsigned)((nw * 40 + p * 8) * 80) + bOff4; \
            ldmx4(bb, baddr);                                                   \
            mma16816(acc[p], ah, bb);                                           \
            mma16816(acc[p], ah, bb + 2);                                       \
            mma16816(acc[p], al, bb);                                           \
        }                                                                       \
    }

// ---------------- batched GEMM: 4 jobs; job 0 fuses attn layer2 + logits ----------------
// dyn smem: As 20480 @0, Bs 25600 @20480, H1big 102400 @46080 -> 148480
#define GEMMA_SMEM 148480

__global__ __launch_bounds__(512, 1) void gemmA(
    const float* __restrict__ states, const float* __restrict__ embeds,
    float* __restrict__ AP, float* __restrict__ BP,
    float* __restrict__ PP, float* __restrict__ LG,
    const float* __restrict__ ab3)
{
    extern __shared__ char smc[];
    __nv_bfloat16* As    = (__nv_bfloat16*)smc;
    __nv_bfloat16* Bs    = (__nv_bfloat16*)(smc + 20480);
    __nv_bfloat16* H1big = (__nv_bfloat16*)(smc + 46080);
    __shared__ float red2[256];
    __shared__ float bmax[4];

    const float* X; int ldx, Kreal, chunks; const __nv_bfloat16* img;
    float* Y;
    switch (blockIdx.y) {
        case 0: X = states; ldx = 400; Kreal = 400; chunks = 25;
                img = g_Wimg + O_A1; Y = nullptr; break;
        case 1: X = states; ldx = 400; Kreal = 400; chunks = 25;
                img = g_Wimg + O_SA; Y = AP; break;
        case 2: X = states; ldx = 400; Kreal = 400; chunks = 25;
                img = g_Wimg + O_SB; Y = BP; break;
        default: X = embeds; ldx = 300; Kreal = 300; chunks = 19;
                img = g_Wimg + O_SP; Y = PP; break;
    }
    const int M = T_TOK;
    const int tid  = threadIdx.x;
    const int lane = tid & 31;
    const int warp = tid >> 5;
    const int mw   = warp & 7;
    const int nw   = warp >> 3;
    const int m0   = blockIdx.x * 128;

    float acc[10][4];
#pragma unroll
    for (int t = 0; t < 10; t++)
#pragma unroll
        for (int j = 0; j < 4; j++) acc[t][j] = 0.f;

    const int aRow = (lane & 7) + ((lane & 8) ? 8 : 0);
    const unsigned aOff = (unsigned)((mw * 16 + aRow) * 80 + ((lane & 16) ? 16 : 0));
    const int bRow = (lane & 7) + ((lane & 16) ? 8 : 0);
    const unsigned bOff = (unsigned)(bRow * 80 + ((lane & 8) ? 16 : 0));
    const unsigned asBase = cvta_s(As);
    const unsigned bsBase = cvta_s(Bs);

    stage_A128(X, ldx, Kreal, m0, M, 0, As, tid);
    stage_B_async(img, 0, Bs, tid);
    CP_COMMIT;
    CP_WAIT_ALL;
    __syncthreads();

    for (int c = 0; c < chunks; c++) {
        int cur = c & 1;
        if (c + 1 < chunks) {
            stage_A128(X, ldx, Kreal, m0, M, c + 1, As + (cur ^ 1) * 5120, tid);
            stage_B_async(img, c + 1, Bs + (cur ^ 1) * 6400, tid);
            CP_COMMIT;
        }
        unsigned aBuf = asBase + cur * 10240;
        unsigned bBuf = bsBase + cur * 12800;
        MMA_CHUNK(aBuf, bBuf);
        if (c + 1 < chunks) CP_WAIT_ALL;
        __syncthreads();
    }

    const int rloc  = mw * 16 + (lane >> 2);
    const int cBase = nw * 80 + 2 * (lane & 3);

    if (blockIdx.y != 0) {
        const int r1 = m0 + rloc;
#pragma unroll
        for (int t = 0; t < 10; t++) {
            int col = cBase + t * 8;
            float2 vA = make_float2(acc[t][0], acc[t][1]);
            float2 vB = make_float2(acc[t][2], acc[t][3]);
            if (r1 < M)     *(float2*)(Y + (size_t)r1 * LDO + col)       = vA;
            if (r1 + 8 < M) *(float2*)(Y + (size_t)(r1 + 8) * LDO + col) = vB;
        }
        return;
    }

    // ===== job 0: fused attention layer-2 + logits =====
#pragma unroll
    for (int t = 0; t < 10; t++) {
        int col = cBase + t * 8;
        float b0 = g_ba1[col], b1v = g_ba1[col + 1];
        float vA0 = fmaxf(acc[t][0] + b0,  0.f);
        float vA1 = fmaxf(acc[t][1] + b1v, 0.f);
        float vB0 = fmaxf(acc[t][2] + b0,  0.f);
        float vB1 = fmaxf(acc[t][3] + b1v, 0.f);
        int cch = col >> 4, kk = col & 15;
        unsigned short h, l;
        unsigned short* rowA = (unsigned short*)(H1big + (size_t)(cch * 128 + rloc) * 40);
        unsigned short* rowB = (unsigned short*)(H1big + (size_t)(cch * 128 + rloc + 8) * 40);
        split_bf16(vA0, h, l); rowA[kk] = h;     rowA[16 + kk] = l;
        split_bf16(vA1, h, l); rowA[kk + 1] = h; rowA[17 + kk] = l;
        split_bf16(vB0, h, l); rowB[kk] = h;     rowB[16 + kk] = l;
        split_bf16(vB1, h, l); rowB[kk + 1] = h; rowB[17 + kk] = l;
    }
    __syncthreads();

    const unsigned h1bigBase = cvta_s(H1big);
#pragma unroll
    for (int t = 0; t < 10; t++)
#pragma unroll
        for (int j = 0; j < 4; j++) acc[t][j] = 0.f;

    stage_B_async(g_Wimg + O_A2, 0, Bs, tid);
    CP_COMMIT;
    CP_WAIT_ALL;
    __syncthreads();
    for (int c = 0; c < 10; c++) {
        int cur = c & 1;
        if (c + 1 < 10) {
            stage_B_async(g_Wimg + O_A2, c + 1, Bs + (cur ^ 1) * 6400, tid);
            CP_COMMIT;
        }
        unsigned aBuf = h1bigBase + (unsigned)(c * 10240);
        unsigned bBuf = bsBase + cur * 12800;
        MMA_CHUNK(aBuf, bBuf);
        if (c + 1 < 10) CP_WAIT_ALL;
        __syncthreads();
    }

    float s1 = 0.f, s2 = 0.f;
#pragma unroll
    for (int t = 0; t < 10; t++) {
        int col = cBase + t * 8;
        float2 b2 = *(const float2*)(g_ba2 + col);
        float2 w3 = *(const float2*)(g_wa3 + col);
        s1 += fmaxf(acc[t][0] + b2.x, 0.f) * w3.x + fmaxf(acc[t][1] + b2.y, 0.f) * w3.y;
        s2 += fmaxf(acc[t][2] + b2.x, 0.f) * w3.x + fmaxf(acc[t][3] + b2.y, 0.f) * w3.y;
    }
    s1 += __shfl_xor_sync(0xffffffffu, s1, 1);
    s1 += __shfl_xor_sync(0xffffffffu, s1, 2);
    s2 += __shfl_xor_sync(0xffffffffu, s2, 1);
    s2 += __shfl_xor_sync(0xffffffffu, s2, 2);
    if ((lane & 3) == 0) {
        red2[rloc * 2 + nw]       = s1;
        red2[(rloc + 8) * 2 + nw] = s2;
    }
    __syncthreads();
    if (tid < 128) {
        int m = m0 + tid;
        float v = red2[tid * 2] + red2[tid * 2 + 1] + ab3[0];
        float mv = -3.4e38f;
        if (m < M) { LG[m] = v; mv = v; }
#pragma unroll
        for (int o = 16; o; o >>= 1) mv = fmaxf(mv, __shfl_xor_sync(0xffffffffu, mv, o));
        if ((tid & 31) == 0) bmax[tid >> 5] = mv;
    }
    __syncthreads();
    if (tid == 0)
        atomicMax(&g_maxbits, encf(fmaxf(fmaxf(bmax[0], bmax[1]),
                                         fmaxf(bmax[2], bmax[3]))));
}

// ---------------- persistent span kernel (R11/R9 version — known good) ----------------
// smem: W2s 128000 @0, H1s 51200 @128000, NS 40960 @179200, eg 320 @220160,
//       sD 256 @220480, invD 256 @220736, red 1024 @220992 -> 222016
#define SPAN_SMEM 222016
#define N_UNITS (313 * 3)

__global__ __launch_bounds__(512, 1) void span_k(
    const float* __restrict__ AP, const float* __restrict__ BP,
    const float* __restrict__ PP, const float* __restrict__ LG,
    const float* __restrict__ b3, float* __restrict__ out)
{
    extern __shared__ char sm[];
    __nv_bfloat16* W2s = (__nv_bfloat16*)sm;
    __nv_bfloat16* H1s = (__nv_bfloat16*)(sm + 128000);
    float* NS   = (float*)(sm + 179200);
    float* eg   = (float*)(sm + 220160);
    float* sD   = (float*)(sm + 220480);
    float* invD = (float*)(sm + 220736);
    float* red  = (float*)(sm + 220992);
    __shared__ int s_u;

    const int tid  = threadIdx.x;
    const int lane = tid & 31;
    const int warp = tid >> 5;
    const int mw   = warp & 3;   // 16-row group
    const int nw   = warp >> 2;  // 40-col group (0..3)

    const int aRow = (lane & 7) + ((lane & 8) ? 8 : 0);
    const unsigned aOff = (unsigned)((mw * 16 + aRow) * 80 + ((lane & 16) ? 16 : 0));
    const unsigned bOff4 = (unsigned)((lane & 7) * 80 + (((lane >> 3) & 3) * 16));
    const unsigned h1Base = cvta_s(H1s);
    const unsigned w2Base = cvta_s(W2s);

    // load full W2 image (128 KB) once
    {
        const float4* src = (const float4*)(g_Wimg + O_W2);
        float4* dst = (float4*)W2s;
        for (int i = tid; i < 8000; i += 512) dst[i] = src[i];
    }

    const float Mx = decf(g_maxbits);

    while (true) {
        if (tid == 0) s_u = atomicAdd(&g_ctr, 1);
        __syncthreads();
        int u = s_u;
        if (u >= N_UNITS) break;
        int tile = u / 3;
        int grp  = u - tile * 3;
        int s0 = tile * 64;
        int n0   = (grp == 0) ? 1 : (grp == 1 ? 5 : 8);
        int nend = (grp == 0) ? 5 : (grp == 1 ? 8 : 11);

        if (tid < 80) {
            int t = s0 + tid;
            eg[tid] = (t < T_TOK) ? __expf(LG[t] - Mx) : 0.f;
        }
        __syncthreads();

        // init NS (numerator for width n0) and sD/invD
#pragma unroll
        for (int it = 0; it < 5; it++) {
            int idx = tid + it * 512;
            int i = idx / 40, g = idx - i * 40, c0 = g * 4;
            float4 a = make_float4(0.f, 0.f, 0.f, 0.f);
            for (int j = 0; j < n0; j++) {
                float e = eg[i + j];
                float4 p = *(const float4*)(PP + (size_t)(s0 + i + j) * LDO + c0);
                a.x += e * p.x; a.y += e * p.y;
                a.z += e * p.z; a.w += e * p.w;
            }
            *(float4*)(NS + i * 160 + c0) = a;
        }
        if (tid < 64) {
            float d = 0.f;
            for (int j = 0; j < n0; j++) d += eg[tid + j];
            sD[tid] = d;
            invD[tid] = 1.f / d;
        }
        __syncthreads();

        for (int n = n0; n < nend; n++) {
            const int S = T_TOK - n + 1;

            // build H1 = relu(AP[s] + BP[s+n-1] + b1 + NS*invD) -> hi/lo split
#pragma unroll
            for (int it = 0; it < 5; it++) {
                int idx = tid + it * 512;
                int i = idx / 40, g = idx - i * 40, c0 = g * 4;
                int s = s0 + i;
                float4 v = make_float4(0.f, 0.f, 0.f, 0.f);
                if (s < S) {
                    float4 a4 = *(const float4*)(AP + (size_t)s * LDO + c0);
                    float4 q4 = *(const float4*)(BP + (size_t)(s + n - 1) * LDO + c0);
                    float4 b4 = *(const float4*)(g_b1 + c0);
                    float4 ns = *(const float4*)(NS + i * 160 + c0);
                    float id = invD[i];
                    v.x = fmaxf(a4.x + q4.x + b4.x + ns.x * id, 0.f);
                    v.y = fmaxf(a4.y + q4.y + b4.y + ns.y * id, 0.f);
                    v.z = fmaxf(a4.z + q4.z + b4.z + ns.z * id, 0.f);
                    v.w = fmaxf(a4.w + q4.w + b4.w + ns.w * id, 0.f);
                }
                unsigned short h[4], l[4];
                split_bf16(v.x, h[0], l[0]); split_bf16(v.y, h[1], l[1]);
                split_bf16(v.z, h[2], l[2]); split_bf16(v.w, h[3], l[3]);
                int cch = g >> 2, kk = (g & 3) * 4;
                unsigned short* dst = (unsigned short*)(H1s + (size_t)(cch * 64 + i) * 40 + kk);
                *(uint2*)dst        = make_uint2((unsigned)h[0] | ((unsigned)h[1] << 16),
                                                 (unsigned)h[2] | ((unsigned)h[3] << 16));
                *(uint2*)(dst + 16) = make_uint2((unsigned)l[0] | ((unsigned)l[1] << 16),
                                                 (unsigned)l[2] | ((unsigned)l[3] << 16));
            }
            __syncthreads();

            // MMA: W2 and H1 resident, 16-warp split, fused hi/lo B loads
            float acc[5][4];
#pragma unroll
            for (int t = 0; t < 5; t++)
#pragma unroll
                for (int j = 0; j < 4; j++) acc[t][j] = 0.f;
#pragma unroll
            for (int c = 0; c < 10; c++) {
                unsigned aBuf = h1Base + (unsigned)(c * 5120);
                unsigned bBuf = w2Base + (unsigned)(c * 12800);
                MMA_CHUNK_W(aBuf, bBuf);
            }

            // epilogue: relu(H2 + b2) . w3, reduce
            const int cBase = nw * 40 + 2 * (lane & 3);
            float s1 = 0.f, s2 = 0.f;
#pragma unroll
            for (int p = 0; p < 5; p++) {
                int col = cBase + p * 8;
                float2 w3 = *(const float2*)(g_w3 + col);
                float2 b2 = *(const float2*)(g_b2 + col);
                s1 += fmaxf(acc[p][0] + b2.x, 0.f) * w3.x + fmaxf(acc[p][1] + b2.y, 0.f) * w3.y;
                s2 += fmaxf(acc[p][2] + b2.x, 0.f) * w3.x + fmaxf(acc[p][3] + b2.y, 0.f) * w3.y;
            }
            s1 += __shfl_xor_sync(0xffffffffu, s1, 1);
            s1 += __shfl_xor_sync(0xffffffffu, s1, 2);
            s2 += __shfl_xor_sync(0xffffffffu, s2, 1);
            s2 += __shfl_xor_sync(0xffffffffu, s2, 2);
            if ((lane & 3) == 0) {
                int row = mw * 16 + (lane >> 2);
                red[row * 4 + nw]       = s1;
                red[(row + 8) * 4 + nw] = s2;
            }
            __syncthreads();

            if (tid < 64) {
                int s = s0 + tid;
                if (s < S) {
                    long long off = (long long)(n - 1) * (T_TOK + 1)
                                  - (long long)(n - 1) * n / 2;
                    out[off + s] = red[tid * 4] + red[tid * 4 + 1]
                                 + red[tid * 4 + 2] + red[tid * 4 + 3] + b3[0];
                }
            }

            // incremental update for next width
            if (n + 1 < nend) {
#pragma unroll
                for (int it = 0; it < 5; it++) {
                    int idx = tid + it * 512;
                    int i = idx / 40, g = idx - i * 40, c0 = g * 4;
                    float e = eg[i + n];
                    float4 p = *(const float4*)(PP + (size_t)(s0 + i + n) * LDO + c0);
                    float4 ns = *(const float4*)(NS + i * 160 + c0);
                    ns.x += e * p.x; ns.y += e * p.y;
                    ns.z += e * p.z; ns.w += e * p.w;
                    *(float4*)(NS + i * 160 + c0) = ns;
                }
                if (tid < 64) {
                    sD[tid] += eg[tid + n];
                    invD[tid] = 1.f / sD[tid];
                }
            }
            __syncthreads();
        }
    }
}

// ---------------- host ----------------
extern "C" void kernel_launch(void* const* d_in, const int* in_sizes, int n_in,
                              void* d_out, int out_size)
{
    const float* embeds  = (const float*)d_in[0];
    const float* states  = (const float*)d_in[1];
    const float* attn_W1 = (const float*)d_in[2];
    const float* attn_b1 = (const float*)d_in[3];
    const float* attn_W2 = (const float*)d_in[4];
    const float* attn_b2 = (const float*)d_in[5];
    const float* attn_W3 = (const float*)d_in[6];
    const float* attn_b3 = (const float*)d_in[7];
    const float* sc_W1   = (const float*)d_in[8];
    const float* sc_b1   = (const float*)d_in[9];
    const float* sc_W2   = (const float*)d_in[10];
    const float* sc_b2   = (const float*)d_in[11];
    const float* sc_W3   = (const float*)d_in[12];
    const float* sc_b3   = (const float*)d_in[13];
    float* out = (float*)d_out;

    float *AP, *BP, *PP, *LG;
    cudaGetSymbolAddress((void**)&AP,  g_AP);
    cudaGetSymbolAddress((void**)&BP,  g_BP);
    cudaGetSymbolAddress((void**)&PP,  g_PP);
    cudaGetSymbolAddress((void**)&LG,  g_LG);

    const int gm128 = (T_TOK + 127) / 128;  // 157

    prep_all<<<148, 256>>>(attn_W1, sc_W1, attn_W2, sc_W2,
                           attn_b1, attn_b2, sc_b1, sc_b2, sc_W3, attn_W3);

    cudaFuncSetAttribute(gemmA, cudaFuncAttributeMaxDynamicSharedMemorySize, GEMMA_SMEM);
    gemmA<<<dim3(gm128, 4), 512, GEMMA_SMEM>>>(states, embeds, AP, BP, PP, LG, attn_b3);

    cudaFuncSetAttribute(span_k, cudaFuncAttributeMaxDynamicSharedMemorySize, SPAN_SMEM);
    span_k<<<148, 512, SPAN_SMEM>>>(AP, BP, PP, LG, sc_b3, out);
}